// round 3
// baseline (speedup 1.0000x reference)
#include <cuda_runtime.h>
#include <cuda_bf16.h>

// Problem constants
#define B_   2
#define NC_  5
#define DHW_ 2457600   // 96*160*160
#define N4_  (DHW_/4)  // 614400 float4 groups per (b, channel)

// Scratch: [b][j], j: 0..19 = s_sum(k=j/4, ch=j%4+1), 20..39 = t_sum, 40..44 = nvox(k)
__device__ double g_acc[B_][45];

__global__ void kd_zero_kernel() {
    int t = threadIdx.x;
    if (t < B_ * 45) ((double*)g_acc)[t] = 0.0;
}

__global__ __launch_bounds__(256)
void kd_accum_kernel(const float* __restrict__ src,
                     const float* __restrict__ tgt,
                     const int* __restrict__ gt) {
    const int b = blockIdx.y;

    // Register-private bins: 5 classes x 4 channels (channels 1..4), s and t, + counts
    float accS[5][4];
    float accT[5][4];
    float accN[5];
#pragma unroll
    for (int i = 0; i < 5; i++) {
        accN[i] = 0.f;
#pragma unroll
        for (int c = 0; c < 4; c++) { accS[i][c] = 0.f; accT[i][c] = 0.f; }
    }

    const float* Sb = src + (size_t)b * NC_ * DHW_;
    const float* Tb = tgt + (size_t)b * NC_ * DHW_;
    const float4* s1p = (const float4*)(Sb + 1 * (size_t)DHW_);
    const float4* s2p = (const float4*)(Sb + 2 * (size_t)DHW_);
    const float4* s3p = (const float4*)(Sb + 3 * (size_t)DHW_);
    const float4* s4p = (const float4*)(Sb + 4 * (size_t)DHW_);
    const float4* t1p = (const float4*)(Tb + 1 * (size_t)DHW_);
    const float4* t2p = (const float4*)(Tb + 2 * (size_t)DHW_);
    const float4* t3p = (const float4*)(Tb + 3 * (size_t)DHW_);
    const float4* t4p = (const float4*)(Tb + 4 * (size_t)DHW_);
    // gt is int32 in the serialized inputs: 4 labels per int4
    const int4* g4 = (const int4*)(gt + (size_t)b * DHW_);

    const int stride = gridDim.x * blockDim.x;

    auto acc1 = [&](int k, float a0, float a1, float a2, float a3,
                           float b0, float b1, float b2, float b3) {
#pragma unroll
        for (int i = 0; i < 5; i++) {
            float m = (k == i) ? 1.0f : 0.0f;
            accN[i]    += m;
            accS[i][0] += m * a0;
            accS[i][1] += m * a1;
            accS[i][2] += m * a2;
            accS[i][3] += m * a3;
            accT[i][0] += m * b0;
            accT[i][1] += m * b1;
            accT[i][2] += m * b2;
            accT[i][3] += m * b3;
        }
    };

    for (int i = blockIdx.x * blockDim.x + threadIdx.x; i < N4_; i += stride) {
        int4 g  = __ldcs(g4 + i);
        float4 s1 = __ldcs(s1p + i);
        float4 s2 = __ldcs(s2p + i);
        float4 s3 = __ldcs(s3p + i);
        float4 s4 = __ldcs(s4p + i);
        float4 t1 = __ldcs(t1p + i);
        float4 t2 = __ldcs(t2p + i);
        float4 t3 = __ldcs(t3p + i);
        float4 t4 = __ldcs(t4p + i);

        acc1(g.x, s1.x, s2.x, s3.x, s4.x, t1.x, t2.x, t3.x, t4.x);
        acc1(g.y, s1.y, s2.y, s3.y, s4.y, t1.y, t2.y, t3.y, t4.y);
        acc1(g.z, s1.z, s2.z, s3.z, s4.z, t1.z, t2.z, t3.z, t4.z);
        acc1(g.w, s1.w, s2.w, s3.w, s4.w, t1.w, t2.w, t3.w, t4.w);
    }

    // ---- warp reduction (deterministic tree within warp) ----
    const unsigned FULL = 0xffffffffu;
#pragma unroll
    for (int off = 16; off > 0; off >>= 1) {
#pragma unroll
        for (int i = 0; i < 5; i++) {
            accN[i] += __shfl_down_sync(FULL, accN[i], off);
#pragma unroll
            for (int c = 0; c < 4; c++) {
                accS[i][c] += __shfl_down_sync(FULL, accS[i][c], off);
                accT[i][c] += __shfl_down_sync(FULL, accT[i][c], off);
            }
        }
    }

    __shared__ float red[8][46];
    const int w = threadIdx.x >> 5;
    const int lane = threadIdx.x & 31;
    if (lane == 0) {
#pragma unroll
        for (int i = 0; i < 5; i++) {
#pragma unroll
            for (int c = 0; c < 4; c++) {
                red[w][i * 4 + c]      = accS[i][c];
                red[w][20 + i * 4 + c] = accT[i][c];
            }
            red[w][40 + i] = accN[i];
        }
    }
    __syncthreads();

    if (threadIdx.x < 45) {
        float s = 0.f;
        const int nw = blockDim.x >> 5;
        for (int ww = 0; ww < nw; ww++) s += red[ww][threadIdx.x];
        atomicAdd(&g_acc[b][threadIdx.x], (double)s);
    }
}

__global__ void kd_final_kernel(float* __restrict__ out) {
    if (threadIdx.x != 0 || blockIdx.x != 0) return;
    double total = 0.0;
    for (int k = 0; k < 5; k++) {
        // nvox is summed over BOTH batches (reference sums onehot over axis 1..4,
        // where axis 1 is the batch axis) and shared by both batches' averages.
        double nvox = g_acc[0][40 + k] + g_acc[1][40 + k];
        double denom = (nvox + 1e-6) * 2.0;  // (nvox+eps) * temperature
        for (int b = 0; b < B_; b++) {
            double sl[4], tl[4];
            for (int c = 0; c < 4; c++) {
                sl[c] = g_acc[b][k * 4 + c] / denom;
                tl[c] = g_acc[b][20 + k * 4 + c] / denom;
            }
            // log_softmax over c
            double ms = sl[0], mt = tl[0];
            for (int c = 1; c < 4; c++) {
                if (sl[c] > ms) ms = sl[c];
                if (tl[c] > mt) mt = tl[c];
            }
            double es = 0.0, et = 0.0;
            for (int c = 0; c < 4; c++) { es += exp(sl[c] - ms); et += exp(tl[c] - mt); }
            double lses = ms + log(es), lset = mt + log(et);
            for (int c = 0; c < 4; c++) {
                double slp = sl[c] - lses;
                double tlp = tl[c] - lset;
                total += exp(tlp) * (tlp - slp) + exp(slp) * (slp - tlp);
            }
        }
    }
    // /batch(2) for each kl, *0.5 avg of the pair, mean over 5 classes => /20
    out[0] = (float)(total / 20.0);
}

extern "C" void kernel_launch(void* const* d_in, const int* in_sizes, int n_in,
                              void* d_out, int out_size) {
    const float* src = (const float*)d_in[0];
    const float* tgt = (const float*)d_in[1];
    const int* gt = (const int*)d_in[2];
    float* out = (float*)d_out;

    kd_zero_kernel<<<1, 128>>>();
    dim3 grid(592, B_);
    kd_accum_kernel<<<grid, 256>>>(src, tgt, gt);
    kd_final_kernel<<<1, 32>>>(out);
}

// round 4
// speedup vs baseline: 1.0317x; 1.0317x over previous
#include <cuda_runtime.h>
#include <cuda_bf16.h>

// Problem constants
#define B_   2
#define NC_  5
#define DHW_ 2457600   // 96*160*160
#define N4_  (DHW_/4)  // 614400 float4 groups per (b, channel)

// Scratch: [by][j], by = b*2 + h (h: 0=source, 1=target)
// j: 0..19 = sum(k=j/4, ch=j%4+1), 20..24 = voxel count per class
// Zero-initialized at module load; kd_final_kernel re-zeros after consuming,
// so every kernel_launch invocation (and graph replay) starts from zeros.
__device__ double g_acc[4][25];

__global__ __launch_bounds__(256)
void kd_accum_kernel(const float* __restrict__ src,
                     const float* __restrict__ tgt,
                     const int* __restrict__ gt) {
    const int by = blockIdx.y;
    const int b = by >> 1;
    const int h = by & 1;

    // Register-private bins: 5 classes x 4 channels + 5 counts = 25 floats
    float acc[5][4];
    float accN[5];
#pragma unroll
    for (int i = 0; i < 5; i++) {
        accN[i] = 0.f;
#pragma unroll
        for (int c = 0; c < 4; c++) acc[i][c] = 0.f;
    }

    const float* base = (h ? tgt : src) + (size_t)b * NC_ * DHW_;
    const float4* p1 = (const float4*)(base + 1 * (size_t)DHW_);
    const float4* p2 = (const float4*)(base + 2 * (size_t)DHW_);
    const float4* p3 = (const float4*)(base + 3 * (size_t)DHW_);
    const float4* p4 = (const float4*)(base + 4 * (size_t)DHW_);
    const int4* g4 = (const int4*)(gt + (size_t)b * DHW_);

    const int stride = gridDim.x * blockDim.x;

    for (int i = blockIdx.x * blockDim.x + threadIdx.x; i < N4_; i += stride) {
        int4   g  = __ldcs(g4 + i);
        float4 v1 = __ldcs(p1 + i);
        float4 v2 = __ldcs(p2 + i);
        float4 v3 = __ldcs(p3 + i);
        float4 v4 = __ldcs(p4 + i);

#pragma unroll
        for (int k = 0; k < 5; k++) {
            float m;
            m = (g.x == k) ? 1.0f : 0.0f;
            accN[k]    += m;
            acc[k][0]  += m * v1.x;
            acc[k][1]  += m * v2.x;
            acc[k][2]  += m * v3.x;
            acc[k][3]  += m * v4.x;
            m = (g.y == k) ? 1.0f : 0.0f;
            accN[k]    += m;
            acc[k][0]  += m * v1.y;
            acc[k][1]  += m * v2.y;
            acc[k][2]  += m * v3.y;
            acc[k][3]  += m * v4.y;
            m = (g.z == k) ? 1.0f : 0.0f;
            accN[k]    += m;
            acc[k][0]  += m * v1.z;
            acc[k][1]  += m * v2.z;
            acc[k][2]  += m * v3.z;
            acc[k][3]  += m * v4.z;
            m = (g.w == k) ? 1.0f : 0.0f;
            accN[k]    += m;
            acc[k][0]  += m * v1.w;
            acc[k][1]  += m * v2.w;
            acc[k][2]  += m * v3.w;
            acc[k][3]  += m * v4.w;
        }
    }

    // ---- warp reduction (deterministic tree) ----
    const unsigned FULL = 0xffffffffu;
#pragma unroll
    for (int off = 16; off > 0; off >>= 1) {
#pragma unroll
        for (int i = 0; i < 5; i++) {
            accN[i] += __shfl_down_sync(FULL, accN[i], off);
#pragma unroll
            for (int c = 0; c < 4; c++)
                acc[i][c] += __shfl_down_sync(FULL, acc[i][c], off);
        }
    }

    __shared__ float red[8][26];
    const int w = threadIdx.x >> 5;
    const int lane = threadIdx.x & 31;
    if (lane == 0) {
#pragma unroll
        for (int i = 0; i < 5; i++) {
#pragma unroll
            for (int c = 0; c < 4; c++) red[w][i * 4 + c] = acc[i][c];
            red[w][20 + i] = accN[i];
        }
    }
    __syncthreads();

    if (threadIdx.x < 25) {
        float s = 0.f;
        const int nw = blockDim.x >> 5;
        for (int ww = 0; ww < nw; ww++) s += red[ww][threadIdx.x];
        atomicAdd(&g_acc[by][threadIdx.x], (double)s);
    }
}

__global__ void kd_final_kernel(float* __restrict__ out) {
    if (threadIdx.x != 0 || blockIdx.x != 0) return;
    double total = 0.0;
    for (int k = 0; k < 5; k++) {
        // nvox is summed over BOTH batches (onehot summed over axes 1..4,
        // axis 1 = batch) and shared by both batches' averages.
        // Counts come from the source halves (by = 0 and 2).
        double nvox = g_acc[0][20 + k] + g_acc[2][20 + k];
        double denom = (nvox + 1e-6) * 2.0;  // (nvox + eps) * temperature
        for (int b = 0; b < B_; b++) {
            double sl[4], tl[4];
            for (int c = 0; c < 4; c++) {
                sl[c] = g_acc[b * 2 + 0][k * 4 + c] / denom;
                tl[c] = g_acc[b * 2 + 1][k * 4 + c] / denom;
            }
            double ms = sl[0], mt = tl[0];
            for (int c = 1; c < 4; c++) {
                if (sl[c] > ms) ms = sl[c];
                if (tl[c] > mt) mt = tl[c];
            }
            double es = 0.0, et = 0.0;
            for (int c = 0; c < 4; c++) { es += exp(sl[c] - ms); et += exp(tl[c] - mt); }
            double lses = ms + log(es), lset = mt + log(et);
            for (int c = 0; c < 4; c++) {
                double slp = sl[c] - lses;
                double tlp = tl[c] - lset;
                total += exp(tlp) * (tlp - slp) + exp(slp) * (slp - tlp);
            }
        }
    }
    // /batch(2) per KL, *0.5 for the pair average, mean over 5 classes => /20
    out[0] = (float)(total / 20.0);

    // Re-zero scratch so the next invocation / graph replay starts clean.
    double* p = (double*)g_acc;
    for (int j = 0; j < 4 * 25; j++) p[j] = 0.0;
}

extern "C" void kernel_launch(void* const* d_in, const int* in_sizes, int n_in,
                              void* d_out, int out_size) {
    const float* src = (const float*)d_in[0];
    const float* tgt = (const float*)d_in[1];
    const int* gt = (const int*)d_in[2];
    float* out = (float*)d_out;

    dim3 grid(592, 4);
    kd_accum_kernel<<<grid, 256>>>(src, tgt, gt);
    kd_final_kernel<<<1, 1>>>(out);
}

// round 5
// speedup vs baseline: 3.9894x; 3.8668x over previous
#include <cuda_runtime.h>
#include <cuda_bf16.h>

// Problem constants
#define B_   2
#define NC_  5
#define DHW_ 2457600   // 96*160*160
#define N4_  (DHW_/4)  // 614400 float4 groups per (b, channel)

// Scratch: [by][j], by = b*2 + h (h: 0=source, 1=target)
// j: 0..19 = sum(k=j/4, ch=j%4+1), 20..24 = voxel count per class
// Zero-initialized at module load; kd_final_kernel re-zeros after consuming.
__device__ double g_acc[4][25];

__global__ __launch_bounds__(256)
void kd_accum_kernel(const float* __restrict__ src,
                     const float* __restrict__ tgt,
                     const int* __restrict__ gt) {
    const int by = blockIdx.y;
    const int b = by >> 1;
    const int h = by & 1;

    float acc[5][4];
    float accN[5];
#pragma unroll
    for (int i = 0; i < 5; i++) {
        accN[i] = 0.f;
#pragma unroll
        for (int c = 0; c < 4; c++) acc[i][c] = 0.f;
    }

    const float* base = (h ? tgt : src) + (size_t)b * NC_ * DHW_;
    const float4* p1 = (const float4*)(base + 1 * (size_t)DHW_);
    const float4* p2 = (const float4*)(base + 2 * (size_t)DHW_);
    const float4* p3 = (const float4*)(base + 3 * (size_t)DHW_);
    const float4* p4 = (const float4*)(base + 4 * (size_t)DHW_);
    const int4* g4 = (const int4*)(gt + (size_t)b * DHW_);

    const int stride = gridDim.x * blockDim.x;

    for (int i = blockIdx.x * blockDim.x + threadIdx.x; i < N4_; i += stride) {
        int4   g  = __ldcs(g4 + i);
        float4 v1 = __ldcs(p1 + i);
        float4 v2 = __ldcs(p2 + i);
        float4 v3 = __ldcs(p3 + i);
        float4 v4 = __ldcs(p4 + i);

#pragma unroll
        for (int k = 0; k < 5; k++) {
            float m;
            m = (g.x == k) ? 1.0f : 0.0f;
            accN[k]   += m;
            acc[k][0] += m * v1.x;
            acc[k][1] += m * v2.x;
            acc[k][2] += m * v3.x;
            acc[k][3] += m * v4.x;
            m = (g.y == k) ? 1.0f : 0.0f;
            accN[k]   += m;
            acc[k][0] += m * v1.y;
            acc[k][1] += m * v2.y;
            acc[k][2] += m * v3.y;
            acc[k][3] += m * v4.y;
            m = (g.z == k) ? 1.0f : 0.0f;
            accN[k]   += m;
            acc[k][0] += m * v1.z;
            acc[k][1] += m * v2.z;
            acc[k][2] += m * v3.z;
            acc[k][3] += m * v4.z;
            m = (g.w == k) ? 1.0f : 0.0f;
            accN[k]   += m;
            acc[k][0] += m * v1.w;
            acc[k][1] += m * v2.w;
            acc[k][2] += m * v3.w;
            acc[k][3] += m * v4.w;
        }
    }

    // ---- warp reduction (deterministic tree) ----
    const unsigned FULL = 0xffffffffu;
#pragma unroll
    for (int off = 16; off > 0; off >>= 1) {
#pragma unroll
        for (int i = 0; i < 5; i++) {
            accN[i] += __shfl_down_sync(FULL, accN[i], off);
#pragma unroll
            for (int c = 0; c < 4; c++)
                acc[i][c] += __shfl_down_sync(FULL, acc[i][c], off);
        }
    }

    __shared__ float red[8][26];
    const int w = threadIdx.x >> 5;
    const int lane = threadIdx.x & 31;
    if (lane == 0) {
#pragma unroll
        for (int i = 0; i < 5; i++) {
#pragma unroll
            for (int c = 0; c < 4; c++) red[w][i * 4 + c] = acc[i][c];
            red[w][20 + i] = accN[i];
        }
    }
    __syncthreads();

    if (threadIdx.x < 25) {
        float s = 0.f;
        const int nw = blockDim.x >> 5;
        for (int ww = 0; ww < nw; ww++) s += red[ww][threadIdx.x];
        atomicAdd(&g_acc[by][threadIdx.x], (double)s);
    }
}

// exp(u) for |u| <= 0.125 via degree-8 Taylor (abs err ~2e-14); libm fallback otherwise.
__device__ __forceinline__ double fast_exp_small(double u) {
    if (fabs(u) > 0.125) return exp(u);
    double r = 1.0 / 40320.0;
    r = fma(r, u, 1.0 / 5040.0);
    r = fma(r, u, 1.0 / 720.0);
    r = fma(r, u, 1.0 / 120.0);
    r = fma(r, u, 1.0 / 24.0);
    r = fma(r, u, 1.0 / 6.0);
    r = fma(r, u, 0.5);
    r = fma(r, u, 1.0);
    r = fma(r, u, 1.0);
    return r;
}

// log(es) where es is near 4: log4 + 2*atanh(w), w = v/(2+v), v = (es-4)/4.
__device__ __forceinline__ double fast_log_near4(double es) {
    double v = (es - 4.0) * 0.25;
    if (fabs(v) > 0.125) return log(es);
    double w = v / (2.0 + v);
    double w2 = w * w;
    double r = 1.0 / 9.0;
    r = fma(r, w2, 1.0 / 7.0);
    r = fma(r, w2, 1.0 / 5.0);
    r = fma(r, w2, 1.0 / 3.0);
    r = fma(r, w2, 1.0);
    // 2*ln(2) = ln(4)
    return fma(2.0 * w, r, 1.3862943611198906188);
}

__global__ __launch_bounds__(32)
void kd_final_kernel(float* __restrict__ out) {
    const int t = threadIdx.x;
    double my = 0.0;

    if (t < 10) {
        const int k = t >> 1;   // class
        const int b = t & 1;    // batch

        // nvox summed over BOTH batches (onehot summed over axes 1..4, axis 1 = batch),
        // shared by both batches' averages. Counts live in the source halves (by=0,2).
        double nvox = g_acc[0][20 + k] + g_acc[2][20 + k];
        double denom = (nvox + 1e-6) * 2.0;  // (nvox + eps) * temperature
        double inv = 1.0 / denom;

        double sl[4], tl[4];
#pragma unroll
        for (int c = 0; c < 4; c++) {
            sl[c] = g_acc[b * 2 + 0][k * 4 + c] * inv;
            tl[c] = g_acc[b * 2 + 1][k * 4 + c] * inv;
        }
        double ms = sl[0], mt = tl[0];
#pragma unroll
        for (int c = 1; c < 4; c++) {
            if (sl[c] > ms) ms = sl[c];
            if (tl[c] > mt) mt = tl[c];
        }
        double esx[4], etx[4], es = 0.0, et = 0.0;
#pragma unroll
        for (int c = 0; c < 4; c++) {
            esx[c] = fast_exp_small(sl[c] - ms);
            etx[c] = fast_exp_small(tl[c] - mt);
            es += esx[c];
            et += etx[c];
        }
        double lses = ms + fast_log_near4(es);
        double lset = mt + fast_log_near4(et);
        double ies = 1.0 / es, iet = 1.0 / et;
#pragma unroll
        for (int c = 0; c < 4; c++) {
            double slp = sl[c] - lses;
            double tlp = tl[c] - lset;
            double pt = etx[c] * iet;   // exp(tlp)
            double ps = esx[c] * ies;   // exp(slp)
            double d = tlp - slp;
            my += pt * d - ps * d;      // pt*(tlp-slp) + ps*(slp-tlp)
        }
    }

    // warp reduction over 10 active contributions
    const unsigned FULL = 0xffffffffu;
#pragma unroll
    for (int off = 16; off > 0; off >>= 1)
        my += __shfl_down_sync(FULL, my, off);

    if (t == 0) {
        // /batch(2) per KL, *0.5 pair average, mean over 5 classes => /20
        out[0] = (float)(my / 20.0);
    }

    __syncthreads();

    // Re-zero scratch so the next invocation / graph replay starts clean.
    double* p = (double*)g_acc;
    for (int j = t; j < 4 * 25; j += 32) p[j] = 0.0;
}

extern "C" void kernel_launch(void* const* d_in, const int* in_sizes, int n_in,
                              void* d_out, int out_size) {
    const float* src = (const float*)d_in[0];
    const float* tgt = (const float*)d_in[1];
    const int* gt = (const int*)d_in[2];
    float* out = (float*)d_out;

    dim3 grid(592, 4);
    kd_accum_kernel<<<grid, 256>>>(src, tgt, gt);
    kd_final_kernel<<<1, 32>>>(out);
}